// round 1
// baseline (speedup 1.0000x reference)
#include <cuda_runtime.h>

#define NN 100000
#define EE 1600000
#define ET (EE + NN)   // edges + self loops

// ---------------- scratch (static device globals; no runtime alloc) --------
__device__ __align__(16) float    g_h[NN * 128];      // projected features
__device__ __align__(16) float    g_agg[NN * 128];    // aggregated output
__device__ __align__(16) float    g_logit[(size_t)ET * 4]; // logits -> e_exp
__device__ __align__(16) float    g_as[NN * 4];
__device__ __align__(16) float    g_ad[NN * 4];
__device__ __align__(16) unsigned g_max[NN * 4];
__device__ __align__(16) float    g_den[NN * 4];

// order-preserving float<->uint encoding for atomicMax
__device__ __forceinline__ unsigned fenc(float f) {
    unsigned u = __float_as_uint(f);
    return (u >> 31) ? ~u : (u | 0x80000000u);
}
__device__ __forceinline__ float fdec(unsigned u) {
    return __uint_as_float((u >> 31) ? (u & 0x7fffffffu) : ~u);
}

__device__ __forceinline__ void red_add_v4(float* p, float4 v) {
    asm volatile("red.global.add.v4.f32 [%0], {%1,%2,%3,%4};"
                 :: "l"(p), "f"(v.x), "f"(v.y), "f"(v.z), "f"(v.w) : "memory");
}

// ---------------- zero init ------------------------------------------------
__global__ void k_zero() {
    int i = blockIdx.x * blockDim.x + threadIdx.x;
    int stride = gridDim.x * blockDim.x;
    float4 z = make_float4(0.f, 0.f, 0.f, 0.f);
    for (int j = i; j < NN * 128 / 4; j += stride) ((float4*)g_agg)[j] = z;
    for (int j = i; j < NN * 4; j += stride) { g_den[j] = 0.f; g_max[j] = 0u; }
}

// ---------------- SGEMM: C[M,128] = op(A)[M,128] @ B[128,128]^T ------------
// MODE 0: plain (h = x @ Wgat^T)
// MODE 1: A' = relu(A + abias[col]); C = A' @ B^T + obias[row]
template <int MODE>
__global__ __launch_bounds__(256)
void k_sgemm(const float* __restrict__ A, const float* __restrict__ B,
             float* __restrict__ C, int M,
             const float* __restrict__ abias, const float* __restrict__ obias) {
    __shared__ float As[16][132];
    __shared__ float Bs[16][132];
    const int tid = threadIdx.x;
    const int m0 = blockIdx.x * 128;
    const int tx = tid & 15;          // output col group
    const int ty = tid >> 4;          // output row group

    float acc[8][8];
#pragma unroll
    for (int i = 0; i < 8; i++)
#pragma unroll
        for (int j = 0; j < 8; j++) acc[i][j] = 0.f;

    for (int kk = 0; kk < 128; kk += 16) {
#pragma unroll
        for (int li = 0; li < 2; li++) {
            int idx = tid * 2 + li;       // 0..511
            int row = idx >> 2;           // 0..127
            int kq  = (idx & 3) * 4;      // 0,4,8,12
            // A tile
            float4 v = make_float4(0.f, 0.f, 0.f, 0.f);
            int gm = m0 + row;
            if (gm < M) v = *(const float4*)&A[gm * 128 + kk + kq];
            if (MODE == 1) {
                v.x = fmaxf(v.x + abias[kk + kq + 0], 0.f);
                v.y = fmaxf(v.y + abias[kk + kq + 1], 0.f);
                v.z = fmaxf(v.z + abias[kk + kq + 2], 0.f);
                v.w = fmaxf(v.w + abias[kk + kq + 3], 0.f);
            }
            As[kq + 0][row] = v.x; As[kq + 1][row] = v.y;
            As[kq + 2][row] = v.z; As[kq + 3][row] = v.w;
            // B tile (B is always 128x128)
            float4 w = *(const float4*)&B[row * 128 + kk + kq];
            Bs[kq + 0][row] = w.x; Bs[kq + 1][row] = w.y;
            Bs[kq + 2][row] = w.z; Bs[kq + 3][row] = w.w;
        }
        __syncthreads();
#pragma unroll
        for (int k = 0; k < 16; k++) {
            float a[8], b[8];
#pragma unroll
            for (int i = 0; i < 8; i++) a[i] = As[k][ty * 8 + i];
#pragma unroll
            for (int j = 0; j < 8; j++) b[j] = Bs[k][tx * 8 + j];
#pragma unroll
            for (int i = 0; i < 8; i++)
#pragma unroll
                for (int j = 0; j < 8; j++) acc[i][j] += a[i] * b[j];
        }
        __syncthreads();
    }

#pragma unroll
    for (int i = 0; i < 8; i++) {
        int gm = m0 + ty * 8 + i;
        if (gm < M) {
#pragma unroll
            for (int j = 0; j < 8; j += 4) {
                int n = tx * 8 + j;
                float4 o;
                o.x = acc[i][j + 0]; o.y = acc[i][j + 1];
                o.z = acc[i][j + 2]; o.w = acc[i][j + 3];
                if (MODE == 1) {
                    o.x += obias[n + 0]; o.y += obias[n + 1];
                    o.z += obias[n + 2]; o.w += obias[n + 3];
                }
                *(float4*)&C[gm * 128 + n] = o;
            }
        }
    }
}

// ---------------- per-node attention scores --------------------------------
__global__ void k_scores(const float* __restrict__ att_s,
                         const float* __restrict__ att_d) {
    int gw = (blockIdx.x * blockDim.x + threadIdx.x) >> 5;
    int lane = threadIdx.x & 31;
    if (gw >= NN) return;
    const float* hp = g_h + (size_t)gw * 128;
#pragma unroll
    for (int hd = 0; hd < 4; hd++) {
        float hv = hp[hd * 32 + lane];
        float ps = hv * att_s[hd * 32 + lane];
        float pd = hv * att_d[hd * 32 + lane];
#pragma unroll
        for (int off = 16; off; off >>= 1) {
            ps += __shfl_xor_sync(0xffffffffu, ps, off);
            pd += __shfl_xor_sync(0xffffffffu, pd, off);
        }
        if (lane == 0) { g_as[gw * 4 + hd] = ps; g_ad[gw * 4 + hd] = pd; }
    }
}

// ---------------- edge pass 1: leaky-relu logits + segment max -------------
__global__ void k_max(const int* __restrict__ ei) {
    int e = blockIdx.x * blockDim.x + threadIdx.x;
    if (e >= ET) return;
    int src, dst;
    if (e < EE) { src = ei[e]; dst = ei[EE + e]; }
    else        { src = dst = e - EE; }
    float4 as = *(const float4*)(g_as + src * 4);
    float4 ad = *(const float4*)(g_ad + dst * 4);
    float4 l;
    l.x = as.x + ad.x; l.x = l.x > 0.f ? l.x : 0.2f * l.x;
    l.y = as.y + ad.y; l.y = l.y > 0.f ? l.y : 0.2f * l.y;
    l.z = as.z + ad.z; l.z = l.z > 0.f ? l.z : 0.2f * l.z;
    l.w = as.w + ad.w; l.w = l.w > 0.f ? l.w : 0.2f * l.w;
    *(float4*)(g_logit + (size_t)e * 4) = l;
    atomicMax(g_max + dst * 4 + 0, fenc(l.x));
    atomicMax(g_max + dst * 4 + 1, fenc(l.y));
    atomicMax(g_max + dst * 4 + 2, fenc(l.z));
    atomicMax(g_max + dst * 4 + 3, fenc(l.w));
}

// ---------------- edge pass 2: exp + segment sum ---------------------------
__global__ void k_exp(const int* __restrict__ ei) {
    int e = blockIdx.x * blockDim.x + threadIdx.x;
    if (e >= ET) return;
    int dst = (e < EE) ? ei[EE + e] : (e - EE);
    float4 l = *(const float4*)(g_logit + (size_t)e * 4);
    uint4 mu = *(const uint4*)(g_max + dst * 4);
    float4 ex;
    ex.x = __expf(l.x - fdec(mu.x));
    ex.y = __expf(l.y - fdec(mu.y));
    ex.z = __expf(l.z - fdec(mu.z));
    ex.w = __expf(l.w - fdec(mu.w));
    *(float4*)(g_logit + (size_t)e * 4) = ex;
    red_add_v4(g_den + dst * 4, ex);
}

// ---------------- edge pass 3: weighted scatter-aggregate ------------------
__global__ void k_scatter(const int* __restrict__ ei) {
    int gw = (blockIdx.x * blockDim.x + threadIdx.x) >> 5;
    int lane = threadIdx.x & 31;
    if (gw >= ET) return;
    int src, dst;
    if (gw < EE) { src = ei[gw]; dst = ei[EE + gw]; }
    else         { src = dst = gw - EE; }
    float4 ex = *(const float4*)(g_logit + (size_t)gw * 4);
    float4 dn = *(const float4*)(g_den + dst * 4);
    float a0 = ex.x / dn.x, a1 = ex.y / dn.y, a2 = ex.z / dn.z, a3 = ex.w / dn.w;
    int hd = lane >> 3;  // 4 consecutive floats per lane -> one head per lane
    float al = hd == 0 ? a0 : hd == 1 ? a1 : hd == 2 ? a2 : a3;
    float4 hv = *(const float4*)(g_h + (size_t)src * 128 + lane * 4);
    float4 v = make_float4(hv.x * al, hv.y * al, hv.z * al, hv.w * al);
    red_add_v4(g_agg + (size_t)dst * 128 + lane * 4, v);
}

// ---------------- launch ---------------------------------------------------
extern "C" void kernel_launch(void* const* d_in, const int* in_sizes, int n_in,
                              void* d_out, int out_size) {
    const float* x    = (const float*)d_in[0];
    const int*   ei   = (const int*)d_in[1];
    const float* Wg   = (const float*)d_in[2];
    const float* asrc = (const float*)d_in[3];
    const float* adst = (const float*)d_in[4];
    const float* bg   = (const float*)d_in[5];
    const float* Wl   = (const float*)d_in[6];
    const float* bl   = (const float*)d_in[7];
    float* out = (float*)d_out;

    void *ph = nullptr, *pagg = nullptr;
    cudaGetSymbolAddress(&ph, g_h);
    cudaGetSymbolAddress(&pagg, g_agg);

    k_zero<<<1184, 256>>>();
    k_sgemm<0><<<(NN + 127) / 128, 256>>>(x, Wg, (float*)ph, NN, nullptr, nullptr);
    k_scores<<<(NN * 32 + 255) / 256, 256>>>(asrc, adst);
    k_max<<<(ET + 255) / 256, 256>>>(ei);
    k_exp<<<(ET + 255) / 256, 256>>>(ei);
    k_scatter<<<(ET * 32 + 255) / 256, 256>>>(ei);
    k_sgemm<1><<<(NN + 127) / 128, 256>>>((const float*)pagg, Wl, out, NN, bg, bl);
}

// round 2
// speedup vs baseline: 1.4224x; 1.4224x over previous
#include <cuda_runtime.h>

#define NN 100000
#define EE 1600000

// ---------------- scratch (static device globals; no runtime alloc) --------
__device__ __align__(16) float g_h[NN * 128];      // projected features
__device__ __align__(16) float g_agg[NN * 128];    // aggregated output
__device__ __align__(16) float g_as[NN * 4];
__device__ __align__(16) float g_ad[NN * 4];
__device__ int g_cnt[NN];
__device__ int g_cur[NN];
__device__ int g_rowptr[NN + 1];
__device__ int g_csr[EE];

// ---------------- zero init (counters only) --------------------------------
__global__ void k_zero() {
    int i = blockIdx.x * blockDim.x + threadIdx.x;
    if (i < NN) { g_cnt[i] = 0; g_cur[i] = 0; }
}

// ---------------- CSR build: count ----------------------------------------
__global__ void k_count(const int* __restrict__ ei) {
    int e = blockIdx.x * blockDim.x + threadIdx.x;
    if (e < EE) atomicAdd(&g_cnt[ei[EE + e]], 1);
}

// ---------------- CSR build: single-block exclusive scan -------------------
__global__ __launch_bounds__(1024) void k_scan() {
    __shared__ int ssum[1024];
    const int t = threadIdx.x;
    const int CH = (NN + 1023) / 1024;       // 98
    int lo = t * CH, hi = min(lo + CH, NN);
    int s = 0;
    for (int i = lo; i < hi; i++) s += g_cnt[i];
    ssum[t] = s;
    __syncthreads();
    for (int off = 1; off < 1024; off <<= 1) {
        int v = 0;
        if (t >= off) v = ssum[t - off];
        __syncthreads();
        if (t >= off) ssum[t] += v;
        __syncthreads();
    }
    int base = (t == 0) ? 0 : ssum[t - 1];
    for (int i = lo; i < hi; i++) { g_rowptr[i] = base; base += g_cnt[i]; }
    if (t == 1023) g_rowptr[NN] = base;      // base == total here (EE)
}

// ---------------- CSR build: fill ------------------------------------------
__global__ void k_fill(const int* __restrict__ ei) {
    int e = blockIdx.x * blockDim.x + threadIdx.x;
    if (e >= EE) return;
    int src = ei[e], dst = ei[EE + e];
    int pos = g_rowptr[dst] + atomicAdd(&g_cur[dst], 1);
    g_csr[pos] = src;
}

// ---------------- SGEMM: C[M,128] = op(A)[M,128] @ B[128,128]^T ------------
// MODE 0: plain (h = x @ Wgat^T)
// MODE 1: A' = relu(A + abias[col]); C = A' @ B^T + obias[row]
template <int MODE>
__global__ __launch_bounds__(256)
void k_sgemm(const float* __restrict__ A, const float* __restrict__ B,
             float* __restrict__ C, int M,
             const float* __restrict__ abias, const float* __restrict__ obias) {
    __shared__ float As[16][132];
    __shared__ float Bs[16][132];
    const int tid = threadIdx.x;
    const int m0 = blockIdx.x * 128;
    const int tx = tid & 15;
    const int ty = tid >> 4;

    float acc[8][8];
#pragma unroll
    for (int i = 0; i < 8; i++)
#pragma unroll
        for (int j = 0; j < 8; j++) acc[i][j] = 0.f;

    for (int kk = 0; kk < 128; kk += 16) {
#pragma unroll
        for (int li = 0; li < 2; li++) {
            int idx = tid * 2 + li;
            int row = idx >> 2;
            int kq  = (idx & 3) * 4;
            float4 v = make_float4(0.f, 0.f, 0.f, 0.f);
            int gm = m0 + row;
            if (gm < M) v = *(const float4*)&A[gm * 128 + kk + kq];
            if (MODE == 1) {
                v.x = fmaxf(v.x + abias[kk + kq + 0], 0.f);
                v.y = fmaxf(v.y + abias[kk + kq + 1], 0.f);
                v.z = fmaxf(v.z + abias[kk + kq + 2], 0.f);
                v.w = fmaxf(v.w + abias[kk + kq + 3], 0.f);
            }
            As[kq + 0][row] = v.x; As[kq + 1][row] = v.y;
            As[kq + 2][row] = v.z; As[kq + 3][row] = v.w;
            float4 w = *(const float4*)&B[row * 128 + kk + kq];
            Bs[kq + 0][row] = w.x; Bs[kq + 1][row] = w.y;
            Bs[kq + 2][row] = w.z; Bs[kq + 3][row] = w.w;
        }
        __syncthreads();
#pragma unroll
        for (int k = 0; k < 16; k++) {
            float a[8], b[8];
#pragma unroll
            for (int i = 0; i < 8; i++) a[i] = As[k][ty * 8 + i];
#pragma unroll
            for (int j = 0; j < 8; j++) b[j] = Bs[k][tx * 8 + j];
#pragma unroll
            for (int i = 0; i < 8; i++)
#pragma unroll
                for (int j = 0; j < 8; j++) acc[i][j] += a[i] * b[j];
        }
        __syncthreads();
    }

#pragma unroll
    for (int i = 0; i < 8; i++) {
        int gm = m0 + ty * 8 + i;
        if (gm < M) {
#pragma unroll
            for (int j = 0; j < 8; j += 4) {
                int n = tx * 8 + j;
                float4 o;
                o.x = acc[i][j + 0]; o.y = acc[i][j + 1];
                o.z = acc[i][j + 2]; o.w = acc[i][j + 3];
                if (MODE == 1) {
                    o.x += obias[n + 0]; o.y += obias[n + 1];
                    o.z += obias[n + 2]; o.w += obias[n + 3];
                }
                *(float4*)&C[gm * 128 + n] = o;
            }
        }
    }
}

// ---------------- per-node attention scores --------------------------------
__global__ void k_scores(const float* __restrict__ att_s,
                         const float* __restrict__ att_d) {
    int gw = (blockIdx.x * blockDim.x + threadIdx.x) >> 5;
    int lane = threadIdx.x & 31;
    if (gw >= NN) return;
    const float* hp = g_h + (size_t)gw * 128;
#pragma unroll
    for (int hd = 0; hd < 4; hd++) {
        float hv = hp[hd * 32 + lane];
        float ps = hv * att_s[hd * 32 + lane];
        float pd = hv * att_d[hd * 32 + lane];
#pragma unroll
        for (int off = 16; off; off >>= 1) {
            ps += __shfl_xor_sync(0xffffffffu, ps, off);
            pd += __shfl_xor_sync(0xffffffffu, pd, off);
        }
        if (lane == 0) { g_as[gw * 4 + hd] = ps; g_ad[gw * 4 + hd] = pd; }
    }
}

// ---------------- fused GAT: online softmax + gather-aggregate -------------
// one warp per destination node
__global__ __launch_bounds__(256) void k_gat() {
    int w = (blockIdx.x * blockDim.x + threadIdx.x) >> 5;
    if (w >= NN) return;
    const int lane = threadIdx.x & 31;
    const int head = lane >> 3;

    const float ad = g_ad[w * 4 + head];

    // self loop seeds the accumulator (weight exp(l_self - m) = 1)
    float l0 = g_as[w * 4 + head] + ad;
    l0 = l0 > 0.f ? l0 : 0.2f * l0;
    float m = l0;
    float s = 1.f;
    float4 acc = ((const float4*)(g_h + (size_t)w * 128))[lane];

    int beg = g_rowptr[w], end = g_rowptr[w + 1];
    int src = (beg < end) ? g_csr[beg] : 0;
    for (int i = beg; i < end; i++) {
        int nxt = (i + 1 < end) ? g_csr[i + 1] : 0;  // prefetch index
        float as = __ldg(&g_as[src * 4 + head]);
        float4 hv = ((const float4*)(g_h + (size_t)src * 128))[lane];
        float le = as + ad;
        le = le > 0.f ? le : 0.2f * le;
        float mn = fmaxf(m, le);
        float c  = __expf(m - mn);
        float wg = __expf(le - mn);
        s = s * c + wg;
        acc.x = acc.x * c + hv.x * wg;
        acc.y = acc.y * c + hv.y * wg;
        acc.z = acc.z * c + hv.z * wg;
        acc.w = acc.w * c + hv.w * wg;
        m = mn;
        src = nxt;
    }
    float inv = 1.f / s;
    acc.x *= inv; acc.y *= inv; acc.z *= inv; acc.w *= inv;
    ((float4*)(g_agg + (size_t)w * 128))[lane] = acc;
}

// ---------------- launch ---------------------------------------------------
extern "C" void kernel_launch(void* const* d_in, const int* in_sizes, int n_in,
                              void* d_out, int out_size) {
    const float* x    = (const float*)d_in[0];
    const int*   ei   = (const int*)d_in[1];
    const float* Wg   = (const float*)d_in[2];
    const float* asrc = (const float*)d_in[3];
    const float* adst = (const float*)d_in[4];
    const float* bg   = (const float*)d_in[5];
    const float* Wl   = (const float*)d_in[6];
    const float* bl   = (const float*)d_in[7];
    float* out = (float*)d_out;

    void *ph = nullptr, *pagg = nullptr;
    cudaGetSymbolAddress(&ph, g_h);
    cudaGetSymbolAddress(&pagg, g_agg);

    k_zero<<<(NN + 255) / 256, 256>>>();
    k_count<<<(EE + 255) / 256, 256>>>(ei);
    k_scan<<<1, 1024>>>();
    k_fill<<<(EE + 255) / 256, 256>>>(ei);
    k_sgemm<0><<<(NN + 127) / 128, 256>>>(x, Wg, (float*)ph, NN, nullptr, nullptr);
    k_scores<<<(NN * 32 + 255) / 256, 256>>>(asrc, adst);
    k_gat<<<(NN * 32 + 255) / 256, 256>>>();
    k_sgemm<1><<<(NN + 127) / 128, 256>>>((const float*)pagg, Wl, out, NN, bg, bl);
}

// round 3
// speedup vs baseline: 2.3369x; 1.6429x over previous
#include <cuda_runtime.h>

#define NN 100000
#define EE 1600000

// ---------------- scratch (static device globals; no runtime alloc) --------
__device__ __align__(16) float g_h[NN * 128];      // projected features
__device__ __align__(16) float g_agg[NN * 128];    // aggregated output
__device__ __align__(16) float g_as[NN * 4];
__device__ __align__(16) float g_ad[NN * 4];
__device__ int g_cnt[NN];
__device__ int g_cur[NN];
__device__ int g_rowptr[NN + 1];
__device__ int g_csr[EE];
__device__ int g_bsum[128];

// ---------------- helpers ---------------------------------------------------
__device__ __forceinline__ unsigned cvt_tf32(float f) {
    unsigned u;
    asm("cvt.rna.tf32.f32 %0, %1;" : "=r"(u) : "f"(f));
    return u;
}

__device__ __forceinline__ void mma_tf32(float (&c)[4], const unsigned (&a)[4],
                                         const unsigned (&b)[2]) {
    asm volatile(
        "mma.sync.aligned.m16n8k8.row.col.f32.tf32.tf32.f32 "
        "{%0,%1,%2,%3}, {%4,%5,%6,%7}, {%8,%9}, {%0,%1,%2,%3};"
        : "+f"(c[0]), "+f"(c[1]), "+f"(c[2]), "+f"(c[3])
        : "r"(a[0]), "r"(a[1]), "r"(a[2]), "r"(a[3]), "r"(b[0]), "r"(b[1]));
}

// ---------------- zero init (counters only) --------------------------------
__global__ void k_zero() {
    int i = blockIdx.x * blockDim.x + threadIdx.x;
    if (i < NN) { g_cnt[i] = 0; g_cur[i] = 0; }
}

// ---------------- CSR build: count ----------------------------------------
__global__ void k_count(const int* __restrict__ ei) {
    int e = blockIdx.x * blockDim.x + threadIdx.x;
    if (e < EE) atomicAdd(&g_cnt[ei[EE + e]], 1);
}

// ---------------- CSR build: 3-level parallel exclusive scan ---------------
__global__ __launch_bounds__(1024) void k_scan1() {
    __shared__ int sh[1024];
    int t = threadIdx.x;
    int i = blockIdx.x * 1024 + t;
    int v = (i < NN) ? g_cnt[i] : 0;
    sh[t] = v;
    __syncthreads();
#pragma unroll
    for (int off = 1; off < 1024; off <<= 1) {
        int u = (t >= off) ? sh[t - off] : 0;
        __syncthreads();
        sh[t] += u;
        __syncthreads();
    }
    if (i < NN) g_rowptr[i] = sh[t] - v;     // chunk-local exclusive
    if (t == 1023) g_bsum[blockIdx.x] = sh[t];
}

__global__ __launch_bounds__(128) void k_scan2() {
    __shared__ int sh[128];
    int t = threadIdx.x;
    int nb = (NN + 1023) / 1024;             // 98
    int v = (t < nb) ? g_bsum[t] : 0;
    sh[t] = v;
    __syncthreads();
#pragma unroll
    for (int off = 1; off < 128; off <<= 1) {
        int u = (t >= off) ? sh[t - off] : 0;
        __syncthreads();
        sh[t] += u;
        __syncthreads();
    }
    if (t < nb) g_bsum[t] = sh[t] - v;       // exclusive chunk offsets
}

__global__ __launch_bounds__(1024) void k_scan3() {
    int i = blockIdx.x * 1024 + threadIdx.x;
    if (i < NN) g_rowptr[i] += g_bsum[blockIdx.x];
    if (i == 0) g_rowptr[NN] = EE;
}

// ---------------- CSR build: fill ------------------------------------------
__global__ void k_fill(const int* __restrict__ ei) {
    int e = blockIdx.x * blockDim.x + threadIdx.x;
    if (e >= EE) return;
    int src = ei[e], dst = ei[EE + e];
    int pos = g_rowptr[dst] + atomicAdd(&g_cur[dst], 1);
    g_csr[pos] = src;
}

// ---------------- TF32 tensor-core GEMM ------------------------------------
// C[M,128] = op(A)[M,128] @ B[128,128]^T   (B row-major [n][k])
// MODE 0: plain. MODE 1: A' = relu(A + abias[col]); C += obias[col].
// 512 threads = 16 warps (4m x 4n), warp tile 32x32, atoms m16n8k8.
template <int MODE>
__global__ __launch_bounds__(512)
void k_gemm(const float* __restrict__ A, const float* __restrict__ B,
            float* __restrict__ C, int M,
            const float* __restrict__ abias, const float* __restrict__ obias) {
    __shared__ uint4 As4[8][128];   // [k/4][m], word = k&3
    __shared__ uint4 Bs4[8][128];   // [k/4][n]
    const unsigned* As_ = (const unsigned*)As4;
    const unsigned* Bs_ = (const unsigned*)Bs4;

    const int tid  = threadIdx.x;
    const int warp = tid >> 5;
    const int lane = tid & 31;
    const int g = lane >> 2;        // group id 0..7
    const int c = lane & 3;         // thread-in-group 0..3
    const int m0 = blockIdx.x * 128;
    const int wm = (warp >> 2) * 32;    // 0,32,64,96
    const int wn = (warp & 3) * 32;     // 0,32,64,96

    float acc[2][4][4];
#pragma unroll
    for (int mi = 0; mi < 2; mi++)
#pragma unroll
        for (int ni = 0; ni < 4; ni++)
#pragma unroll
            for (int j = 0; j < 4; j++) acc[mi][ni][j] = 0.f;

#pragma unroll
    for (int kt = 0; kt < 4; kt++) {
        const int kk = kt * 32;
        __syncthreads();
        // load tiles: 1024 float4 each, 512 threads x 2
#pragma unroll
        for (int l = 0; l < 2; l++) {
            int idx = l * 512 + tid;         // 0..1023
            int row = idx >> 3;              // 0..127
            int kq  = (idx & 7) << 2;        // 0..28
            // A
            float4 v = make_float4(0.f, 0.f, 0.f, 0.f);
            if (m0 + row < M) v = *(const float4*)&A[(size_t)(m0 + row) * 128 + kk + kq];
            if (MODE == 1) {
                v.x = fmaxf(v.x + abias[kk + kq + 0], 0.f);
                v.y = fmaxf(v.y + abias[kk + kq + 1], 0.f);
                v.z = fmaxf(v.z + abias[kk + kq + 2], 0.f);
                v.w = fmaxf(v.w + abias[kk + kq + 3], 0.f);
            }
            uint4 pa;
            pa.x = cvt_tf32(v.x); pa.y = cvt_tf32(v.y);
            pa.z = cvt_tf32(v.z); pa.w = cvt_tf32(v.w);
            As4[kq >> 2][row] = pa;
            // B
            float4 w = *(const float4*)&B[(size_t)row * 128 + kk + kq];
            uint4 pb;
            pb.x = cvt_tf32(w.x); pb.y = cvt_tf32(w.y);
            pb.z = cvt_tf32(w.z); pb.w = cvt_tf32(w.w);
            Bs4[kq >> 2][row] = pb;
        }
        __syncthreads();

#pragma unroll
        for (int ka = 0; ka < 4; ka++) {
            const int k0 = ka * 8;
            unsigned af[2][4];
#pragma unroll
            for (int mi = 0; mi < 2; mi++) {
                int mr = wm + mi * 16;
                af[mi][0] = As_[((k0 + c) >> 2) * 512 + (mr + g) * 4 + ((k0 + c) & 3)];
                af[mi][1] = As_[((k0 + c) >> 2) * 512 + (mr + g + 8) * 4 + ((k0 + c) & 3)];
                af[mi][2] = As_[((k0 + c + 4) >> 2) * 512 + (mr + g) * 4 + ((k0 + c + 4) & 3)];
                af[mi][3] = As_[((k0 + c + 4) >> 2) * 512 + (mr + g + 8) * 4 + ((k0 + c + 4) & 3)];
            }
            unsigned bf[4][2];
#pragma unroll
            for (int ni = 0; ni < 4; ni++) {
                int nc = wn + ni * 8 + g;
                bf[ni][0] = Bs_[((k0 + c) >> 2) * 512 + nc * 4 + ((k0 + c) & 3)];
                bf[ni][1] = Bs_[((k0 + c + 4) >> 2) * 512 + nc * 4 + ((k0 + c + 4) & 3)];
            }
#pragma unroll
            for (int mi = 0; mi < 2; mi++)
#pragma unroll
                for (int ni = 0; ni < 4; ni++)
                    mma_tf32(acc[mi][ni], af[mi], bf[ni]);
        }
    }

    // epilogue
#pragma unroll
    for (int mi = 0; mi < 2; mi++) {
#pragma unroll
        for (int ni = 0; ni < 4; ni++) {
            int col = wn + ni * 8 + 2 * c;
            float2 v0 = make_float2(acc[mi][ni][0], acc[mi][ni][1]);
            float2 v1 = make_float2(acc[mi][ni][2], acc[mi][ni][3]);
            if (MODE == 1) {
                float2 ob = *(const float2*)&obias[col];
                v0.x += ob.x; v0.y += ob.y;
                v1.x += ob.x; v1.y += ob.y;
            }
            int r0 = m0 + wm + mi * 16 + g;
            int r1 = r0 + 8;
            if (r0 < M) *(float2*)&C[(size_t)r0 * 128 + col] = v0;
            if (r1 < M) *(float2*)&C[(size_t)r1 * 128 + col] = v1;
        }
    }
}

// ---------------- per-node attention scores --------------------------------
__global__ void k_scores(const float* __restrict__ att_s,
                         const float* __restrict__ att_d) {
    int gw = (blockIdx.x * blockDim.x + threadIdx.x) >> 5;
    int lane = threadIdx.x & 31;
    if (gw >= NN) return;
    const float* hp = g_h + (size_t)gw * 128;
#pragma unroll
    for (int hd = 0; hd < 4; hd++) {
        float hv = hp[hd * 32 + lane];
        float ps = hv * att_s[hd * 32 + lane];
        float pd = hv * att_d[hd * 32 + lane];
#pragma unroll
        for (int off = 16; off; off >>= 1) {
            ps += __shfl_xor_sync(0xffffffffu, ps, off);
            pd += __shfl_xor_sync(0xffffffffu, pd, off);
        }
        if (lane == 0) { g_as[gw * 4 + hd] = ps; g_ad[gw * 4 + hd] = pd; }
    }
}

// ---------------- fused GAT: online softmax + gather-aggregate -------------
// one warp per destination node
__global__ __launch_bounds__(256) void k_gat() {
    int w = (blockIdx.x * blockDim.x + threadIdx.x) >> 5;
    if (w >= NN) return;
    const int lane = threadIdx.x & 31;
    const int head = lane >> 3;

    const float ad = g_ad[w * 4 + head];

    // self loop seeds the accumulator (weight exp(l_self - m) = 1)
    float l0 = g_as[w * 4 + head] + ad;
    l0 = l0 > 0.f ? l0 : 0.2f * l0;
    float m = l0;
    float s = 1.f;
    float4 acc = ((const float4*)(g_h + (size_t)w * 128))[lane];

    int beg = g_rowptr[w], end = g_rowptr[w + 1];
    int src = (beg < end) ? g_csr[beg] : 0;
    for (int i = beg; i < end; i++) {
        int nxt = (i + 1 < end) ? g_csr[i + 1] : 0;  // prefetch index
        float as = __ldg(&g_as[src * 4 + head]);
        float4 hv = ((const float4*)(g_h + (size_t)src * 128))[lane];
        float le = as + ad;
        le = le > 0.f ? le : 0.2f * le;
        float mn = fmaxf(m, le);
        float cc = __expf(m - mn);
        float wg = __expf(le - mn);
        s = s * cc + wg;
        acc.x = acc.x * cc + hv.x * wg;
        acc.y = acc.y * cc + hv.y * wg;
        acc.z = acc.z * cc + hv.z * wg;
        acc.w = acc.w * cc + hv.w * wg;
        m = mn;
        src = nxt;
    }
    float inv = 1.f / s;
    acc.x *= inv; acc.y *= inv; acc.z *= inv; acc.w *= inv;
    ((float4*)(g_agg + (size_t)w * 128))[lane] = acc;
}

// ---------------- launch ---------------------------------------------------
extern "C" void kernel_launch(void* const* d_in, const int* in_sizes, int n_in,
                              void* d_out, int out_size) {
    const float* x    = (const float*)d_in[0];
    const int*   ei   = (const int*)d_in[1];
    const float* Wg   = (const float*)d_in[2];
    const float* asrc = (const float*)d_in[3];
    const float* adst = (const float*)d_in[4];
    const float* bg   = (const float*)d_in[5];
    const float* Wl   = (const float*)d_in[6];
    const float* bl   = (const float*)d_in[7];
    float* out = (float*)d_out;

    void *ph = nullptr, *pagg = nullptr;
    cudaGetSymbolAddress(&ph, g_h);
    cudaGetSymbolAddress(&pagg, g_agg);

    const int nchunk = (NN + 1023) / 1024;

    k_zero<<<(NN + 255) / 256, 256>>>();
    k_count<<<(EE + 255) / 256, 256>>>(ei);
    k_scan1<<<nchunk, 1024>>>();
    k_scan2<<<1, 128>>>();
    k_scan3<<<nchunk, 1024>>>();
    k_fill<<<(EE + 255) / 256, 256>>>(ei);
    k_gemm<0><<<(NN + 127) / 128, 512>>>(x, Wg, (float*)ph, NN, nullptr, nullptr);
    k_scores<<<(NN * 32 + 255) / 256, 256>>>(asrc, adst);
    k_gat<<<(NN * 32 + 255) / 256, 256>>>();
    k_gemm<1><<<(NN + 127) / 128, 512>>>((const float*)pagg, Wl, out, NN, bg, bl);
}